// round 12
// baseline (speedup 1.0000x reference)
#include <cuda_runtime.h>
#include <math.h>

// ---------------------------------------------------------------------------
// GATv2Conv layer. N=50000, E=800000, D=128, H=4, C=32.
// R12 = R11 (320.2us) + k_logit v3 micro-ops:
//   - sea staged PRE-DUPLICATED as packed f32x2 (kills 32 pk movs/pair)
//   - xl/xr gathered as ulonglong2 (kills 8 repack pk/pair)
//   - packed leaky-relu 0.6u+0.4|u| (and.b64 + mul2 + fma2)
//   - packed attention dot
// Everything else identical to R11. k_logit stays in profiled slot 3.
// ---------------------------------------------------------------------------

#define MAX_N 50000
#define MAX_E 800000
#define SCAN_B 1024
#define GP 68                      // xs row pad (floats); 272B rows, 16B aligned
#define EPB 256                    // edges per block-tile in k_logit

typedef unsigned long long ull;

__device__ int   g_is64;
__device__ float g_xl[(size_t)MAX_N * 128];
__device__ float g_xr[(size_t)MAX_N * 128];
__device__ float g_logit[(size_t)MAX_E * 4];   // [e][h]
__device__ int   g_count[MAX_N];
__device__ int   g_rowptr[MAX_N + 1];
__device__ int   g_cursor[MAX_N];
__device__ int2  g_edata[MAX_E];     // CSR payload: {src, eid}
__device__ int   g_blocksum[64];

// ---- packed f32x2 helpers (Blackwell) ----
__device__ __forceinline__ ull pk(float lo, float hi) {
    ull r; asm("mov.b64 %0,{%1,%2};" : "=l"(r) : "f"(lo), "f"(hi)); return r;
}
__device__ __forceinline__ void upk(ull v, float& lo, float& hi) {
    asm("mov.b64 {%0,%1},%2;" : "=f"(lo), "=f"(hi) : "l"(v));
}
__device__ __forceinline__ ull ffma2(ull a, ull b, ull c) {
    ull d; asm("fma.rn.f32x2 %0,%1,%2,%3;" : "=l"(d) : "l"(a), "l"(b), "l"(c)); return d;
}
__device__ __forceinline__ ull fadd2(ull a, ull b) {
    ull d; asm("add.rn.f32x2 %0,%1,%2;" : "=l"(d) : "l"(a), "l"(b)); return d;
}
__device__ __forceinline__ ull fmul2(ull a, ull b) {
    ull d; asm("mul.rn.f32x2 %0,%1,%2;" : "=l"(d) : "l"(a), "l"(b)); return d;
}

__device__ __forceinline__ int ld_idx(const void* ei, long long i, int is64) {
    if (is64) return (int)((const long long*)ei)[i];
    return ((const int*)ei)[i];
}

__device__ __forceinline__ float4 ldcs4(const float4* p) {
    float4 v;
    asm("ld.global.cs.v4.f32 {%0,%1,%2,%3},[%4];"
        : "=f"(v.x), "=f"(v.y), "=f"(v.z), "=f"(v.w) : "l"(p));
    return v;
}
__device__ __forceinline__ int2 ldcs2i(const int2* p) {
    int2 v;
    asm("ld.global.cs.v2.s32 {%0,%1},[%2];" : "=r"(v.x), "=r"(v.y) : "l"(p));
    return v;
}

// ---------------------------------------------------------------------------
__global__ void kinit(const unsigned int* __restrict__ w, int E, int N) {
    int i = blockIdx.x * blockDim.x + threadIdx.x;
    if (i < N) g_count[i] = 0;
    if (blockIdx.x == 0 && threadIdx.x < 32) {
        int lane = threadIdx.x;
        int bad = 0;
        int n = E < 64 ? E : 64;
        for (int j = lane; j < n; j += 32)
            if (w[2 * j + 1] != 0u) bad = 1;
        unsigned any = __ballot_sync(0xffffffffu, bad);
        if (lane == 0) g_is64 = (any == 0u);
    }
}

__global__ void khist(const void* __restrict__ ei, int E) {
    int e = blockIdx.x * blockDim.x + threadIdx.x;
    if (e >= E) return;
    int dst = ld_idx(ei, (long long)E + e, g_is64);
    atomicAdd(&g_count[dst], 1);
}

__global__ void kscan1(int N) {
    __shared__ int red[32];
    int t = threadIdx.x;
    int idx = blockIdx.x * SCAN_B + t;
    int v = (idx < N) ? g_count[idx] : 0;
#pragma unroll
    for (int o = 16; o >= 1; o >>= 1) v += __shfl_down_sync(0xffffffffu, v, o);
    if ((t & 31) == 0) red[t >> 5] = v;
    __syncthreads();
    if (t < 32) {
        int u = red[t];
#pragma unroll
        for (int o = 16; o >= 1; o >>= 1) u += __shfl_down_sync(0xffffffffu, u, o);
        if (t == 0) g_blocksum[blockIdx.x] = u;
    }
}

__global__ void kscan3(int N, int nb) {
    __shared__ int wsum[32];
    __shared__ int boff_s;
    int t = threadIdx.x;
    int lane = t & 31, w = t >> 5;
    int idx = blockIdx.x * SCAN_B + t;
    int v = (idx < N) ? g_count[idx] : 0;
    int s = v;
#pragma unroll
    for (int o = 1; o < 32; o <<= 1) {
        int u = __shfl_up_sync(0xffffffffu, s, o);
        if (lane >= o) s += u;
    }
    if (lane == 31) wsum[w] = s;
    __syncthreads();
    if (w == 0) {
        int ws = wsum[lane];
#pragma unroll
        for (int o = 1; o < 32; o <<= 1) {
            int u = __shfl_up_sync(0xffffffffu, ws, o);
            if (lane >= o) ws += u;
        }
        wsum[lane] = ws;
    } else if (w == 1) {
        int bid = blockIdx.x;
        int v1 = (lane < nb && lane < bid) ? g_blocksum[lane] : 0;
        int v2 = (lane + 32 < nb && lane + 32 < bid) ? g_blocksum[lane + 32] : 0;
        int u = v1 + v2;
#pragma unroll
        for (int o = 16; o >= 1; o >>= 1) u += __shfl_down_sync(0xffffffffu, u, o);
        if (lane == 0) boff_s = u;
    }
    __syncthreads();
    int excl = s - v + (w ? wsum[w - 1] : 0) + boff_s;
    if (idx < N) {
        g_rowptr[idx] = excl;
        g_cursor[idx] = excl;
        if (idx == N - 1) g_rowptr[N] = excl + v;
    }
}

__global__ void kscatter(const void* __restrict__ ei, int E) {
    int e = blockIdx.x * blockDim.x + threadIdx.x;
    if (e >= E) return;
    int is64 = g_is64;
    int dst = ld_idx(ei, (long long)E + e, is64);
    int src = ld_idx(ei, e, is64);
    int pos = atomicAdd(&g_cursor[dst], 1);
    g_edata[pos] = make_int2(src, e);
}

// ---------------------------------------------------------------------------
// Register-blocked node transform. Block: 64 nodes x 128 cols (y picks Wl/Wr).
// ---------------------------------------------------------------------------
__global__ __launch_bounds__(256) void k_gemm(
    const float* __restrict__ x,
    const float* __restrict__ Wl, const float* __restrict__ bl,
    const float* __restrict__ Wr, const float* __restrict__ br, int N)
{
    __shared__ __align__(16) float xs[128 * GP];   // [k][n], 34816 B
    __shared__ __align__(16) float ws[16 * 128];   // [k][j], 8192 B
    const int tid = threadIdx.x;
    const int cg = tid & 31;
    const int ng = tid >> 5;
    const int nb = blockIdx.x * 64;
    const float* W   = blockIdx.y ? Wr : Wl;
    const float* bv  = blockIdx.y ? br : bl;
    float* dstp      = blockIdx.y ? g_xr : g_xl;

    for (int q = 0; q < 8; q++) {
        int idx = tid + 256 * q;
        int k = idx & 127, n4 = idx >> 7;
        int n0 = nb + 4 * n4;
        float v0 = 0.f, v1 = 0.f, v2 = 0.f, v3 = 0.f;
        if (n0 + 3 < N) {
            v0 = x[(size_t)(n0 + 0) * 128 + k];
            v1 = x[(size_t)(n0 + 1) * 128 + k];
            v2 = x[(size_t)(n0 + 2) * 128 + k];
            v3 = x[(size_t)(n0 + 3) * 128 + k];
        } else {
            if (n0 + 0 < N) v0 = x[(size_t)(n0 + 0) * 128 + k];
            if (n0 + 1 < N) v1 = x[(size_t)(n0 + 1) * 128 + k];
            if (n0 + 2 < N) v2 = x[(size_t)(n0 + 2) * 128 + k];
            if (n0 + 3 < N) v3 = x[(size_t)(n0 + 3) * 128 + k];
        }
        *(float4*)(xs + k * GP + 4 * n4) = make_float4(v0, v1, v2, v3);
    }

    ull acc[4][4];
#pragma unroll
    for (int a = 0; a < 4; a++)
#pragma unroll
        for (int b = 0; b < 4; b++) acc[a][b] = 0ull;

    for (int kc = 0; kc < 8; kc++) {
        __syncthreads();
        for (int q = 0; q < 2; q++) {
            int idx = tid + 256 * q;
            int k = idx >> 5, j4 = idx & 31;
            *(float4*)(ws + k * 128 + 4 * j4) =
                *(const float4*)(W + (size_t)(kc * 16 + k) * 128 + 4 * j4);
        }
        __syncthreads();
#pragma unroll
        for (int k = 0; k < 16; k++) {
            const float* xrow = xs + (kc * 16 + k) * GP + 8 * ng;
            ulonglong2 xa = *(const ulonglong2*)(xrow);
            ulonglong2 xb = *(const ulonglong2*)(xrow + 4);
            float4 w4 = *(const float4*)(ws + k * 128 + 4 * cg);
            ull wd0 = pk(w4.x, w4.x), wd1 = pk(w4.y, w4.y);
            ull wd2 = pk(w4.z, w4.z), wd3 = pk(w4.w, w4.w);
            acc[0][0] = ffma2(xa.x, wd0, acc[0][0]);
            acc[0][1] = ffma2(xa.x, wd1, acc[0][1]);
            acc[0][2] = ffma2(xa.x, wd2, acc[0][2]);
            acc[0][3] = ffma2(xa.x, wd3, acc[0][3]);
            acc[1][0] = ffma2(xa.y, wd0, acc[1][0]);
            acc[1][1] = ffma2(xa.y, wd1, acc[1][1]);
            acc[1][2] = ffma2(xa.y, wd2, acc[1][2]);
            acc[1][3] = ffma2(xa.y, wd3, acc[1][3]);
            acc[2][0] = ffma2(xb.x, wd0, acc[2][0]);
            acc[2][1] = ffma2(xb.x, wd1, acc[2][1]);
            acc[2][2] = ffma2(xb.x, wd2, acc[2][2]);
            acc[2][3] = ffma2(xb.x, wd3, acc[2][3]);
            acc[3][0] = ffma2(xb.y, wd0, acc[3][0]);
            acc[3][1] = ffma2(xb.y, wd1, acc[3][1]);
            acc[3][2] = ffma2(xb.y, wd2, acc[3][2]);
            acc[3][3] = ffma2(xb.y, wd3, acc[3][3]);
        }
    }

    float4 bvv = *(const float4*)(bv + 4 * cg);
#pragma unroll
    for (int np = 0; np < 4; np++) {
        float l0, h0, l1, h1, l2, h2, l3, h3;
        upk(acc[np][0], l0, h0);
        upk(acc[np][1], l1, h1);
        upk(acc[np][2], l2, h2);
        upk(acc[np][3], l3, h3);
        int n0 = nb + 8 * ng + 2 * np;
        if (n0 < N)
            *(float4*)(dstp + (size_t)n0 * 128 + 4 * cg) =
                make_float4(l0 + bvv.x, l1 + bvv.y, l2 + bvv.z, l3 + bvv.w);
        if (n0 + 1 < N)
            *(float4*)(dstp + (size_t)(n0 + 1) * 128 + 4 * cg) =
                make_float4(h0 + bvv.x, h1 + bvv.y, h2 + bvv.z, h3 + bvv.w);
    }
}

// ---------------------------------------------------------------------------
// k_logit v3: block-tile of EPB=256 edges. sea staged PRE-DUPLICATED as
// packed f32x2 ull (32KB), indices in sidx (2KB). Warp w handles tile edges
// [32w, 32w+32) with ILP-2. Inner loop: ulonglong2 broadcasts + FFMA2 only;
// packed leaky (0.6u + 0.4|u|) and packed att-dot.
// ---------------------------------------------------------------------------
__global__ __launch_bounds__(256, 2) void k_logit(
    const void*  __restrict__ ei,
    const float* __restrict__ ea,
    const float* __restrict__ We,
    const float* __restrict__ attw,
    int E)
{
    __shared__ __align__(16) ull sea[EPB * 16];     // 32 KB, pre-duplicated
    __shared__ int2 sidx[EPB];                      // 2 KB
    const int tid = threadIdx.x;
    const int lane = tid & 31;
    const int w = tid >> 5;
    const int is64 = g_is64;
    const int tile_stride = gridDim.x * EPB;

    ull wA[16], wB[16];
#pragma unroll
    for (int d = 0; d < 16; d++) {
        float4 wv = *(const float4*)(We + (size_t)d * 128 + lane * 4);
        wA[d] = pk(wv.x, wv.y);
        wB[d] = pk(wv.z, wv.w);
    }
    float4 at4 = *(const float4*)(attw + lane * 4);
    const ull at01 = pk(at4.x, at4.y), at23 = pk(at4.z, at4.w);
    const ull C06 = pk(0.6f, 0.6f), C04 = pk(0.4f, 0.4f);
    const ull ABSM = 0x7FFFFFFF7FFFFFFFULL;

    for (int base = blockIdx.x * EPB; base < E; base += tile_stride) {
        __syncthreads();
        // stage ea duplicated: edge = i>>2, quarter = i&3 (one float4 each)
        for (int i = tid; i < EPB * 4; i += 256) {
            int e = base + (i >> 2);
            float4 v = make_float4(0.f, 0.f, 0.f, 0.f);
            if (e < E) v = ldcs4((const float4*)(ea + (size_t)e * 16) + (i & 3));
            ulonglong2* p = (ulonglong2*)(sea + (i >> 2) * 16 + (i & 3) * 4);
            p[0] = make_ulonglong2(pk(v.x, v.x), pk(v.y, v.y));
            p[1] = make_ulonglong2(pk(v.z, v.z), pk(v.w, v.w));
        }
        {
            int e = base + tid;
            int2 sd = make_int2(0, 0);
            if (e < E) {
                sd.x = ld_idx(ei, e, is64);
                sd.y = ld_idx(ei, (long long)E + e, is64);
            }
            sidx[tid] = sd;
        }
        __syncthreads();

#pragma unroll 1
        for (int j = 0; j < 32; j += 2) {
            int lA = w * 32 + j, lB = lA + 1;
            int eA = base + lA, eB = base + lB;
            int2 iA = sidx[lA];
            int2 iB = sidx[lB];
            ulonglong2 xlA = *(const ulonglong2*)(g_xl + (size_t)iA.x * 128 + lane * 4);
            ulonglong2 xrA = *(const ulonglong2*)(g_xr + (size_t)iA.y * 128 + lane * 4);
            ulonglong2 xlB = *(const ulonglong2*)(g_xl + (size_t)iB.x * 128 + lane * 4);
            ulonglong2 xrB = *(const ulonglong2*)(g_xr + (size_t)iB.y * 128 + lane * 4);

            ull aA0 = 0ull, aA1 = 0ull, aB0 = 0ull, aB1 = 0ull;
            const ulonglong2* qA = (const ulonglong2*)(sea + lA * 16);
            const ulonglong2* qB = (const ulonglong2*)(sea + lB * 16);
#pragma unroll
            for (int d2 = 0; d2 < 8; d2++) {
                ulonglong2 a2 = qA[d2];   // broadcast LDS.128: 2 duplicated d values
                ulonglong2 b2 = qB[d2];
                aA0 = ffma2(a2.x, wA[2*d2],   aA0); aA1 = ffma2(a2.x, wB[2*d2],   aA1);
                aB0 = ffma2(b2.x, wA[2*d2],   aB0); aB1 = ffma2(b2.x, wB[2*d2],   aB1);
                aA0 = ffma2(a2.y, wA[2*d2+1], aA0); aA1 = ffma2(a2.y, wB[2*d2+1], aA1);
                aB0 = ffma2(b2.y, wA[2*d2+1], aB0); aB1 = ffma2(b2.y, wB[2*d2+1], aB1);
            }

            ull sA0 = fadd2(fadd2(xlA.x, xrA.x), aA0);
            ull sA1 = fadd2(fadd2(xlA.y, xrA.y), aA1);
            ull sB0 = fadd2(fadd2(xlB.x, xrB.x), aB0);
            ull sB1 = fadd2(fadd2(xlB.y, xrB.y), aB1);

            // packed leaky: 0.6*u + 0.4*|u|  (== max(u, 0.2u))
            sA0 = ffma2(sA0, C06, fmul2(sA0 & ABSM, C04));
            sA1 = ffma2(sA1, C06, fmul2(sA1 & ABSM, C04));
            sB0 = ffma2(sB0, C06, fmul2(sB0 & ABSM, C04));
            sB1 = ffma2(sB1, C06, fmul2(sB1 & ABSM, C04));

            // packed att dot, then horizontal add
            ull pA = ffma2(sA1, at23, fmul2(sA0, at01));
            ull pB = ffma2(sB1, at23, fmul2(sB0, at01));
            float pA0, pA1, pB0, pB1;
            upk(pA, pA0, pA1);
            upk(pB, pB0, pB1);
            float tA = pA0 + pA1;
            float tB = pB0 + pB1;
            tA += __shfl_xor_sync(0xffffffffu, tA, 1);
            tB += __shfl_xor_sync(0xffffffffu, tB, 1);
            tA += __shfl_xor_sync(0xffffffffu, tA, 2);
            tB += __shfl_xor_sync(0xffffffffu, tB, 2);
            tA += __shfl_xor_sync(0xffffffffu, tA, 4);
            tB += __shfl_xor_sync(0xffffffffu, tB, 4);
            if (!(lane & 7)) {
                if (eA < E) g_logit[4 * (size_t)eA + (lane >> 3)] = tA;
                if (eB < E) g_logit[4 * (size_t)eB + (lane >> 3)] = tB;
            }
        }
    }
}

// ---------------------------------------------------------------------------
// Fused per-node kernel: one warp per node, TWO edges in flight.
// ---------------------------------------------------------------------------
__global__ __launch_bounds__(256, 3) void k_fused(
    const float* __restrict__ bias,
    const float* __restrict__ gamma,
    const float* __restrict__ beta,
    const float* __restrict__ x,
    float* __restrict__ out, int N)
{
    const int lane = threadIdx.x & 31;
    const int head = lane >> 3;
    const int wid = (blockIdx.x * blockDim.x + threadIdx.x) >> 5;
    const int nwarps = (gridDim.x * blockDim.x) >> 5;

    for (int n = wid; n < N; n += nwarps) {
        int beg = g_rowptr[n];
        int end = g_rowptr[n + 1];

        ull num01 = 0ull, num23 = 0ull;
        float den = 0.f;

        float4 x0, x1; float l0 = 0.f, l1 = 0.f;
        int2 eA, eB;
        if (beg < end) {
            int2 t0 = ldcs2i(&g_edata[beg]);
            l0 = g_logit[4 * (size_t)t0.y + head];
            x0 = *(const float4*)(g_xl + (size_t)t0.x * 128 + lane * 4);
        }
        if (beg + 1 < end) {
            int2 t1 = ldcs2i(&g_edata[beg + 1]);
            l1 = g_logit[4 * (size_t)t1.y + head];
            x1 = *(const float4*)(g_xl + (size_t)t1.x * 128 + lane * 4);
        }
        if (beg + 2 < end) eA = ldcs2i(&g_edata[beg + 2]);
        if (beg + 3 < end) eB = ldcs2i(&g_edata[beg + 3]);

        int i = beg;
#pragma unroll 1
        while (i + 1 < end) {
            float4 nx0; float nl0 = 0.f;
            int2 eN0;
            if (i + 2 < end) {
                nl0 = g_logit[4 * (size_t)eA.y + head];
                nx0 = *(const float4*)(g_xl + (size_t)eA.x * 128 + lane * 4);
                if (i + 4 < end) eN0 = ldcs2i(&g_edata[i + 4]);
            }
            float4 nx1; float nl1 = 0.f;
            int2 eN1;
            if (i + 3 < end) {
                nl1 = g_logit[4 * (size_t)eB.y + head];
                nx1 = *(const float4*)(g_xl + (size_t)eB.x * 128 + lane * 4);
                if (i + 5 < end) eN1 = ldcs2i(&g_edata[i + 5]);
            }

            float ex0 = __expf(l0);
            float ex1 = __expf(l1);
            den += ex0 + ex1;
            ull e0p = pk(ex0, ex0), e1p = pk(ex1, ex1);
            num01 = ffma2(e0p, pk(x0.x, x0.y), num01);
            num23 = ffma2(e0p, pk(x0.z, x0.w), num23);
            num01 = ffma2(e1p, pk(x1.x, x1.y), num01);
            num23 = ffma2(e1p, pk(x1.z, x1.w), num23);

            x0 = nx0; l0 = nl0;
            x1 = nx1; l1 = nl1;
            eA = eN0; eB = eN1;
            i += 2;
        }
        if (i < end) {
            float ex = __expf(l0);
            den += ex;
            ull exp2 = pk(ex, ex);
            num01 = ffma2(exp2, pk(x0.x, x0.y), num01);
            num23 = ffma2(exp2, pk(x0.z, x0.w), num23);
        }

        float4 b4  = *(const float4*)(bias  + lane * 4);
        float4 g4  = *(const float4*)(gamma + lane * 4);
        float4 be4 = *(const float4*)(beta  + lane * 4);

        float invd = 1.f / (den + 1e-16f);
        float o0, o1, o2, o3;
        upk(num01, o0, o1); upk(num23, o2, o3);
        o0 = o0 * invd + b4.x;
        o1 = o1 * invd + b4.y;
        o2 = o2 * invd + b4.z;
        o3 = o3 * invd + b4.w;
        const float inv_sqrt2 = 0.70710678118654752f;
        o0 = 0.5f * o0 * (1.f + erff(o0 * inv_sqrt2));
        o1 = 0.5f * o1 * (1.f + erff(o1 * inv_sqrt2));
        o2 = 0.5f * o2 * (1.f + erff(o2 * inv_sqrt2));
        o3 = 0.5f * o3 * (1.f + erff(o3 * inv_sqrt2));
        float4 x4 = *(const float4*)(x + (size_t)n * 128 + lane * 4);
        float v0 = o0 + x4.x, v1 = o1 + x4.y, v2 = o2 + x4.z, v3 = o3 + x4.w;

        float s = v0 + v1 + v2 + v3;
        float q = v0 * v0 + v1 * v1 + v2 * v2 + v3 * v3;
#pragma unroll
        for (int m = 16; m >= 1; m >>= 1) {
            s += __shfl_xor_sync(0xffffffffu, s, m);
            q += __shfl_xor_sync(0xffffffffu, q, m);
        }
        float mu = s * (1.f / 128.f);
        float var = q * (1.f / 128.f) - mu * mu;
        float rs = rsqrtf(var + 1e-5f);
        float4 y;
        y.x = (v0 - mu) * rs * g4.x + be4.x;
        y.y = (v1 - mu) * rs * g4.y + be4.y;
        y.z = (v2 - mu) * rs * g4.z + be4.z;
        y.w = (v3 - mu) * rs * g4.w + be4.w;
        *(float4*)(out + (size_t)n * 128 + lane * 4) = y;
    }
}

// ---------------------------------------------------------------------------
extern "C" void kernel_launch(void* const* d_in, const int* in_sizes, int n_in,
                              void* d_out, int out_size)
{
    const float* x    = (const float*)d_in[0];
    const void*  ei   = d_in[1];
    const float* ea   = (const float*)d_in[2];
    const float* Wl   = (const float*)d_in[3];
    const float* bl   = (const float*)d_in[4];
    const float* Wr   = (const float*)d_in[5];
    const float* br   = (const float*)d_in[6];
    const float* We   = (const float*)d_in[7];
    const float* att  = (const float*)d_in[8];
    const float* bias = (const float*)d_in[9];
    const float* gam  = (const float*)d_in[10];
    const float* bet  = (const float*)d_in[11];

    int N = in_sizes[0] / 128;
    int E = in_sizes[1] / 2;
    int nb = (N + SCAN_B - 1) / SCAN_B;

    dim3 ggrid((N + 63) / 64, 2);

    kinit<<<(N + 255) / 256, 256>>>((const unsigned int*)ei, E, N);   // 0
    khist<<<(E + 255) / 256, 256>>>(ei, E);                           // 1
    k_gemm<<<ggrid, 256>>>(x, Wl, bl, Wr, br, N);                     // 2
    k_logit<<<296, 256>>>(ei, ea, We, att, E);                        // 3 (profiled)
    kscan1<<<nb, SCAN_B>>>(N);                                        // 4
    kscan3<<<nb, SCAN_B>>>(N, nb);                                    // 5
    kscatter<<<(E + 255) / 256, 256>>>(ei, E);                        // 6
    k_fused<<<444, 256>>>(bias, gam, bet, x, (float*)d_out, N);       // 7
}

// round 13
// speedup vs baseline: 1.0945x; 1.0945x over previous
#include <cuda_runtime.h>
#include <math.h>

// ---------------------------------------------------------------------------
// GATv2Conv layer. N=50000, E=800000, D=128, H=4, C=32.
// R13 = R11 (320.2us; k_logit reverted from the R12 smem-heavy variant) +
// multi-stream overlap: CSR chain {khist,kscan1,kscan3,kscatter} runs on a
// forked stream concurrently with {k_gemm,k_logit}; event-join before k_fused.
// Fork/join uses the documented capture-legal event pattern.
// ---------------------------------------------------------------------------

#define MAX_N 50000
#define MAX_E 800000
#define SCAN_B 1024
#define GP 68                      // xs row pad (floats); 272B rows, 16B aligned
#define EPB 256                    // edges per block-tile in k_logit

typedef unsigned long long ull;

__device__ int   g_is64;
__device__ float g_xl[(size_t)MAX_N * 128];
__device__ float g_xr[(size_t)MAX_N * 128];
__device__ float g_logit[(size_t)MAX_E * 4];   // [e][h]
__device__ int   g_count[MAX_N];
__device__ int   g_rowptr[MAX_N + 1];
__device__ int   g_cursor[MAX_N];
__device__ int2  g_edata[MAX_E];     // CSR payload: {src, eid}
__device__ int   g_blocksum[64];

// ---- packed f32x2 helpers (Blackwell) ----
__device__ __forceinline__ ull pk(float lo, float hi) {
    ull r; asm("mov.b64 %0,{%1,%2};" : "=l"(r) : "f"(lo), "f"(hi)); return r;
}
__device__ __forceinline__ void upk(ull v, float& lo, float& hi) {
    asm("mov.b64 {%0,%1},%2;" : "=f"(lo), "=f"(hi) : "l"(v));
}
__device__ __forceinline__ ull ffma2(ull a, ull b, ull c) {
    ull d; asm("fma.rn.f32x2 %0,%1,%2,%3;" : "=l"(d) : "l"(a), "l"(b), "l"(c)); return d;
}
__device__ __forceinline__ ull fadd2(ull a, ull b) {
    ull d; asm("add.rn.f32x2 %0,%1,%2;" : "=l"(d) : "l"(a), "l"(b)); return d;
}

__device__ __forceinline__ int ld_idx(const void* ei, long long i, int is64) {
    if (is64) return (int)((const long long*)ei)[i];
    return ((const int*)ei)[i];
}

__device__ __forceinline__ float4 ldcs4(const float4* p) {
    float4 v;
    asm("ld.global.cs.v4.f32 {%0,%1,%2,%3},[%4];"
        : "=f"(v.x), "=f"(v.y), "=f"(v.z), "=f"(v.w) : "l"(p));
    return v;
}
__device__ __forceinline__ int2 ldcs2i(const int2* p) {
    int2 v;
    asm("ld.global.cs.v2.s32 {%0,%1},[%2];" : "=r"(v.x), "=r"(v.y) : "l"(p));
    return v;
}

// ---------------------------------------------------------------------------
__global__ void kinit(const unsigned int* __restrict__ w, int E, int N) {
    int i = blockIdx.x * blockDim.x + threadIdx.x;
    if (i < N) g_count[i] = 0;
    if (blockIdx.x == 0 && threadIdx.x < 32) {
        int lane = threadIdx.x;
        int bad = 0;
        int n = E < 64 ? E : 64;
        for (int j = lane; j < n; j += 32)
            if (w[2 * j + 1] != 0u) bad = 1;
        unsigned any = __ballot_sync(0xffffffffu, bad);
        if (lane == 0) g_is64 = (any == 0u);
    }
}

__global__ void khist(const void* __restrict__ ei, int E) {
    int e = blockIdx.x * blockDim.x + threadIdx.x;
    if (e >= E) return;
    int dst = ld_idx(ei, (long long)E + e, g_is64);
    atomicAdd(&g_count[dst], 1);
}

__global__ void kscan1(int N) {
    __shared__ int red[32];
    int t = threadIdx.x;
    int idx = blockIdx.x * SCAN_B + t;
    int v = (idx < N) ? g_count[idx] : 0;
#pragma unroll
    for (int o = 16; o >= 1; o >>= 1) v += __shfl_down_sync(0xffffffffu, v, o);
    if ((t & 31) == 0) red[t >> 5] = v;
    __syncthreads();
    if (t < 32) {
        int u = red[t];
#pragma unroll
        for (int o = 16; o >= 1; o >>= 1) u += __shfl_down_sync(0xffffffffu, u, o);
        if (t == 0) g_blocksum[blockIdx.x] = u;
    }
}

__global__ void kscan3(int N, int nb) {
    __shared__ int wsum[32];
    __shared__ int boff_s;
    int t = threadIdx.x;
    int lane = t & 31, w = t >> 5;
    int idx = blockIdx.x * SCAN_B + t;
    int v = (idx < N) ? g_count[idx] : 0;
    int s = v;
#pragma unroll
    for (int o = 1; o < 32; o <<= 1) {
        int u = __shfl_up_sync(0xffffffffu, s, o);
        if (lane >= o) s += u;
    }
    if (lane == 31) wsum[w] = s;
    __syncthreads();
    if (w == 0) {
        int ws = wsum[lane];
#pragma unroll
        for (int o = 1; o < 32; o <<= 1) {
            int u = __shfl_up_sync(0xffffffffu, ws, o);
            if (lane >= o) ws += u;
        }
        wsum[lane] = ws;
    } else if (w == 1) {
        int bid = blockIdx.x;
        int v1 = (lane < nb && lane < bid) ? g_blocksum[lane] : 0;
        int v2 = (lane + 32 < nb && lane + 32 < bid) ? g_blocksum[lane + 32] : 0;
        int u = v1 + v2;
#pragma unroll
        for (int o = 16; o >= 1; o >>= 1) u += __shfl_down_sync(0xffffffffu, u, o);
        if (lane == 0) boff_s = u;
    }
    __syncthreads();
    int excl = s - v + (w ? wsum[w - 1] : 0) + boff_s;
    if (idx < N) {
        g_rowptr[idx] = excl;
        g_cursor[idx] = excl;
        if (idx == N - 1) g_rowptr[N] = excl + v;
    }
}

__global__ void kscatter(const void* __restrict__ ei, int E) {
    int e = blockIdx.x * blockDim.x + threadIdx.x;
    if (e >= E) return;
    int is64 = g_is64;
    int dst = ld_idx(ei, (long long)E + e, is64);
    int src = ld_idx(ei, e, is64);
    int pos = atomicAdd(&g_cursor[dst], 1);
    g_edata[pos] = make_int2(src, e);
}

// ---------------------------------------------------------------------------
// Register-blocked node transform. Block: 64 nodes x 128 cols (y picks Wl/Wr).
// ---------------------------------------------------------------------------
__global__ __launch_bounds__(256) void k_gemm(
    const float* __restrict__ x,
    const float* __restrict__ Wl, const float* __restrict__ bl,
    const float* __restrict__ Wr, const float* __restrict__ br, int N)
{
    __shared__ __align__(16) float xs[128 * GP];   // [k][n], 34816 B
    __shared__ __align__(16) float ws[16 * 128];   // [k][j], 8192 B
    const int tid = threadIdx.x;
    const int cg = tid & 31;
    const int ng = tid >> 5;
    const int nb = blockIdx.x * 64;
    const float* W   = blockIdx.y ? Wr : Wl;
    const float* bv  = blockIdx.y ? br : bl;
    float* dstp      = blockIdx.y ? g_xr : g_xl;

    for (int q = 0; q < 8; q++) {
        int idx = tid + 256 * q;
        int k = idx & 127, n4 = idx >> 7;
        int n0 = nb + 4 * n4;
        float v0 = 0.f, v1 = 0.f, v2 = 0.f, v3 = 0.f;
        if (n0 + 3 < N) {
            v0 = x[(size_t)(n0 + 0) * 128 + k];
            v1 = x[(size_t)(n0 + 1) * 128 + k];
            v2 = x[(size_t)(n0 + 2) * 128 + k];
            v3 = x[(size_t)(n0 + 3) * 128 + k];
        } else {
            if (n0 + 0 < N) v0 = x[(size_t)(n0 + 0) * 128 + k];
            if (n0 + 1 < N) v1 = x[(size_t)(n0 + 1) * 128 + k];
            if (n0 + 2 < N) v2 = x[(size_t)(n0 + 2) * 128 + k];
            if (n0 + 3 < N) v3 = x[(size_t)(n0 + 3) * 128 + k];
        }
        *(float4*)(xs + k * GP + 4 * n4) = make_float4(v0, v1, v2, v3);
    }

    ull acc[4][4];
#pragma unroll
    for (int a = 0; a < 4; a++)
#pragma unroll
        for (int b = 0; b < 4; b++) acc[a][b] = 0ull;

    for (int kc = 0; kc < 8; kc++) {
        __syncthreads();
        for (int q = 0; q < 2; q++) {
            int idx = tid + 256 * q;
            int k = idx >> 5, j4 = idx & 31;
            *(float4*)(ws + k * 128 + 4 * j4) =
                *(const float4*)(W + (size_t)(kc * 16 + k) * 128 + 4 * j4);
        }
        __syncthreads();
#pragma unroll
        for (int k = 0; k < 16; k++) {
            const float* xrow = xs + (kc * 16 + k) * GP + 8 * ng;
            ulonglong2 xa = *(const ulonglong2*)(xrow);
            ulonglong2 xb = *(const ulonglong2*)(xrow + 4);
            float4 w4 = *(const float4*)(ws + k * 128 + 4 * cg);
            ull wd0 = pk(w4.x, w4.x), wd1 = pk(w4.y, w4.y);
            ull wd2 = pk(w4.z, w4.z), wd3 = pk(w4.w, w4.w);
            acc[0][0] = ffma2(xa.x, wd0, acc[0][0]);
            acc[0][1] = ffma2(xa.x, wd1, acc[0][1]);
            acc[0][2] = ffma2(xa.x, wd2, acc[0][2]);
            acc[0][3] = ffma2(xa.x, wd3, acc[0][3]);
            acc[1][0] = ffma2(xa.y, wd0, acc[1][0]);
            acc[1][1] = ffma2(xa.y, wd1, acc[1][1]);
            acc[1][2] = ffma2(xa.y, wd2, acc[1][2]);
            acc[1][3] = ffma2(xa.y, wd3, acc[1][3]);
            acc[2][0] = ffma2(xb.x, wd0, acc[2][0]);
            acc[2][1] = ffma2(xb.x, wd1, acc[2][1]);
            acc[2][2] = ffma2(xb.x, wd2, acc[2][2]);
            acc[2][3] = ffma2(xb.x, wd3, acc[2][3]);
            acc[3][0] = ffma2(xb.y, wd0, acc[3][0]);
            acc[3][1] = ffma2(xb.y, wd1, acc[3][1]);
            acc[3][2] = ffma2(xb.y, wd2, acc[3][2]);
            acc[3][3] = ffma2(xb.y, wd3, acc[3][3]);
        }
    }

    float4 bvv = *(const float4*)(bv + 4 * cg);
#pragma unroll
    for (int np = 0; np < 4; np++) {
        float l0, h0, l1, h1, l2, h2, l3, h3;
        upk(acc[np][0], l0, h0);
        upk(acc[np][1], l1, h1);
        upk(acc[np][2], l2, h2);
        upk(acc[np][3], l3, h3);
        int n0 = nb + 8 * ng + 2 * np;
        if (n0 < N)
            *(float4*)(dstp + (size_t)n0 * 128 + 4 * cg) =
                make_float4(l0 + bvv.x, l1 + bvv.y, l2 + bvv.z, l3 + bvv.w);
        if (n0 + 1 < N)
            *(float4*)(dstp + (size_t)(n0 + 1) * 128 + 4 * cg) =
                make_float4(h0 + bvv.x, h1 + bvv.y, h2 + bvv.z, h3 + bvv.w);
    }
}

// ---------------------------------------------------------------------------
// k_logit (R11 version, 146.7us): block-tile of EPB=256 edges, smem staging
// of ea (plain float, 16KB) + indices (2KB), ILP-2 inner loop.
// ---------------------------------------------------------------------------
__global__ __launch_bounds__(256, 2) void k_logit(
    const void*  __restrict__ ei,
    const float* __restrict__ ea,
    const float* __restrict__ We,
    const float* __restrict__ attw,
    int E)
{
    __shared__ __align__(16) float sea[EPB * 16];   // 16 KB
    __shared__ int2 sidx[EPB];                      // 2 KB
    const int tid = threadIdx.x;
    const int lane = tid & 31;
    const int w = tid >> 5;
    const int is64 = g_is64;
    const int tile_stride = gridDim.x * EPB;

    ull wA[16], wB[16];
#pragma unroll
    for (int d = 0; d < 16; d++) {
        float4 wv = *(const float4*)(We + (size_t)d * 128 + lane * 4);
        wA[d] = pk(wv.x, wv.y);
        wB[d] = pk(wv.z, wv.w);
    }
    float4 at4 = *(const float4*)(attw + lane * 4);

    for (int base = blockIdx.x * EPB; base < E; base += tile_stride) {
        __syncthreads();
        for (int i = tid; i < EPB * 4; i += 256) {
            int e = base + (i >> 2);
            float4 v = make_float4(0.f, 0.f, 0.f, 0.f);
            if (e < E) v = ldcs4((const float4*)(ea + (size_t)e * 16) + (i & 3));
            *(float4*)(sea + i * 4) = v;
        }
        {
            int e = base + tid;
            int2 sd = make_int2(0, 0);
            if (e < E) {
                sd.x = ld_idx(ei, e, is64);
                sd.y = ld_idx(ei, (long long)E + e, is64);
            }
            sidx[tid] = sd;
        }
        __syncthreads();

#pragma unroll 1
        for (int j = 0; j < 32; j += 2) {
            int lA = w * 32 + j, lB = lA + 1;
            int eA = base + lA, eB = base + lB;
            int2 iA = sidx[lA];
            int2 iB = sidx[lB];
            float4 xlA = *(const float4*)(g_xl + (size_t)iA.x * 128 + lane * 4);
            float4 xrA = *(const float4*)(g_xr + (size_t)iA.y * 128 + lane * 4);
            float4 xlB = *(const float4*)(g_xl + (size_t)iB.x * 128 + lane * 4);
            float4 xrB = *(const float4*)(g_xr + (size_t)iB.y * 128 + lane * 4);

            ull aA0 = 0ull, aA1 = 0ull, aB0 = 0ull, aB1 = 0ull;
#pragma unroll
            for (int d4 = 0; d4 < 4; d4++) {
                float4 qA = *(const float4*)(sea + lA * 16 + d4 * 4);  // broadcast LDS
                float4 qB = *(const float4*)(sea + lB * 16 + d4 * 4);
                ull t;
                t = pk(qA.x, qA.x); aA0 = ffma2(t, wA[4*d4+0], aA0); aA1 = ffma2(t, wB[4*d4+0], aA1);
                t = pk(qB.x, qB.x); aB0 = ffma2(t, wA[4*d4+0], aB0); aB1 = ffma2(t, wB[4*d4+0], aB1);
                t = pk(qA.y, qA.y); aA0 = ffma2(t, wA[4*d4+1], aA0); aA1 = ffma2(t, wB[4*d4+1], aA1);
                t = pk(qB.y, qB.y); aB0 = ffma2(t, wA[4*d4+1], aB0); aB1 = ffma2(t, wB[4*d4+1], aB1);
                t = pk(qA.z, qA.z); aA0 = ffma2(t, wA[4*d4+2], aA0); aA1 = ffma2(t, wB[4*d4+2], aA1);
                t = pk(qB.z, qB.z); aB0 = ffma2(t, wA[4*d4+2], aB0); aB1 = ffma2(t, wB[4*d4+2], aB1);
                t = pk(qA.w, qA.w); aA0 = ffma2(t, wA[4*d4+3], aA0); aA1 = ffma2(t, wB[4*d4+3], aA1);
                t = pk(qB.w, qB.w); aB0 = ffma2(t, wA[4*d4+3], aB0); aB1 = ffma2(t, wB[4*d4+3], aB1);
            }

            ull sA0 = fadd2(fadd2(pk(xlA.x, xlA.y), pk(xrA.x, xrA.y)), aA0);
            ull sA1 = fadd2(fadd2(pk(xlA.z, xlA.w), pk(xrA.z, xrA.w)), aA1);
            ull sB0 = fadd2(fadd2(pk(xlB.x, xlB.y), pk(xrB.x, xrB.y)), aB0);
            ull sB1 = fadd2(fadd2(pk(xlB.z, xlB.w), pk(xrB.z, xrB.w)), aB1);

            float a0, a1, a2, a3, b0, b1, b2, b3;
            upk(sA0, a0, a1); upk(sA1, a2, a3);
            upk(sB0, b0, b1); upk(sB1, b2, b3);
            a0 = fmaxf(a0, 0.2f * a0); a1 = fmaxf(a1, 0.2f * a1);
            a2 = fmaxf(a2, 0.2f * a2); a3 = fmaxf(a3, 0.2f * a3);
            b0 = fmaxf(b0, 0.2f * b0); b1 = fmaxf(b1, 0.2f * b1);
            b2 = fmaxf(b2, 0.2f * b2); b3 = fmaxf(b3, 0.2f * b3);
            float tA = a0 * at4.x + a1 * at4.y + a2 * at4.z + a3 * at4.w;
            float tB = b0 * at4.x + b1 * at4.y + b2 * at4.z + b3 * at4.w;
            tA += __shfl_xor_sync(0xffffffffu, tA, 1);
            tB += __shfl_xor_sync(0xffffffffu, tB, 1);
            tA += __shfl_xor_sync(0xffffffffu, tA, 2);
            tB += __shfl_xor_sync(0xffffffffu, tB, 2);
            tA += __shfl_xor_sync(0xffffffffu, tA, 4);
            tB += __shfl_xor_sync(0xffffffffu, tB, 4);
            if (!(lane & 7)) {
                if (eA < E) g_logit[4 * (size_t)eA + (lane >> 3)] = tA;
                if (eB < E) g_logit[4 * (size_t)eB + (lane >> 3)] = tB;
            }
        }
    }
}

// ---------------------------------------------------------------------------
// Fused per-node kernel: one warp per node, TWO edges in flight.
// ---------------------------------------------------------------------------
__global__ __launch_bounds__(256, 3) void k_fused(
    const float* __restrict__ bias,
    const float* __restrict__ gamma,
    const float* __restrict__ beta,
    const float* __restrict__ x,
    float* __restrict__ out, int N)
{
    const int lane = threadIdx.x & 31;
    const int head = lane >> 3;
    const int wid = (blockIdx.x * blockDim.x + threadIdx.x) >> 5;
    const int nwarps = (gridDim.x * blockDim.x) >> 5;

    for (int n = wid; n < N; n += nwarps) {
        int beg = g_rowptr[n];
        int end = g_rowptr[n + 1];

        ull num01 = 0ull, num23 = 0ull;
        float den = 0.f;

        float4 x0, x1; float l0 = 0.f, l1 = 0.f;
        int2 eA, eB;
        if (beg < end) {
            int2 t0 = ldcs2i(&g_edata[beg]);
            l0 = g_logit[4 * (size_t)t0.y + head];
            x0 = *(const float4*)(g_xl + (size_t)t0.x * 128 + lane * 4);
        }
        if (beg + 1 < end) {
            int2 t1 = ldcs2i(&g_edata[beg + 1]);
            l1 = g_logit[4 * (size_t)t1.y + head];
            x1 = *(const float4*)(g_xl + (size_t)t1.x * 128 + lane * 4);
        }
        if (beg + 2 < end) eA = ldcs2i(&g_edata[beg + 2]);
        if (beg + 3 < end) eB = ldcs2i(&g_edata[beg + 3]);

        int i = beg;
#pragma unroll 1
        while (i + 1 < end) {
            float4 nx0; float nl0 = 0.f;
            int2 eN0;
            if (i + 2 < end) {
                nl0 = g_logit[4 * (size_t)eA.y + head];
                nx0 = *(const float4*)(g_xl + (size_t)eA.x * 128 + lane * 4);
                if (i + 4 < end) eN0 = ldcs2i(&g_edata[i + 4]);
            }
            float4 nx1; float nl1 = 0.f;
            int2 eN1;
            if (i + 3 < end) {
                nl1 = g_logit[4 * (size_t)eB.y + head];
                nx1 = *(const float4*)(g_xl + (size_t)eB.x * 128 + lane * 4);
                if (i + 5 < end) eN1 = ldcs2i(&g_edata[i + 5]);
            }

            float ex0 = __expf(l0);
            float ex1 = __expf(l1);
            den += ex0 + ex1;
            ull e0p = pk(ex0, ex0), e1p = pk(ex1, ex1);
            num01 = ffma2(e0p, pk(x0.x, x0.y), num01);
            num23 = ffma2(e0p, pk(x0.z, x0.w), num23);
            num01 = ffma2(e1p, pk(x1.x, x1.y), num01);
            num23 = ffma2(e1p, pk(x1.z, x1.w), num23);

            x0 = nx0; l0 = nl0;
            x1 = nx1; l1 = nl1;
            eA = eN0; eB = eN1;
            i += 2;
        }
        if (i < end) {
            float ex = __expf(l0);
            den += ex;
            ull exp2 = pk(ex, ex);
            num01 = ffma2(exp2, pk(x0.x, x0.y), num01);
            num23 = ffma2(exp2, pk(x0.z, x0.w), num23);
        }

        float4 b4  = *(const float4*)(bias  + lane * 4);
        float4 g4  = *(const float4*)(gamma + lane * 4);
        float4 be4 = *(const float4*)(beta  + lane * 4);

        float invd = 1.f / (den + 1e-16f);
        float o0, o1, o2, o3;
        upk(num01, o0, o1); upk(num23, o2, o3);
        o0 = o0 * invd + b4.x;
        o1 = o1 * invd + b4.y;
        o2 = o2 * invd + b4.z;
        o3 = o3 * invd + b4.w;
        const float inv_sqrt2 = 0.70710678118654752f;
        o0 = 0.5f * o0 * (1.f + erff(o0 * inv_sqrt2));
        o1 = 0.5f * o1 * (1.f + erff(o1 * inv_sqrt2));
        o2 = 0.5f * o2 * (1.f + erff(o2 * inv_sqrt2));
        o3 = 0.5f * o3 * (1.f + erff(o3 * inv_sqrt2));
        float4 x4 = *(const float4*)(x + (size_t)n * 128 + lane * 4);
        float v0 = o0 + x4.x, v1 = o1 + x4.y, v2 = o2 + x4.z, v3 = o3 + x4.w;

        float s = v0 + v1 + v2 + v3;
        float q = v0 * v0 + v1 * v1 + v2 * v2 + v3 * v3;
#pragma unroll
        for (int m = 16; m >= 1; m >>= 1) {
            s += __shfl_xor_sync(0xffffffffu, s, m);
            q += __shfl_xor_sync(0xffffffffu, q, m);
        }
        float mu = s * (1.f / 128.f);
        float var = q * (1.f / 128.f) - mu * mu;
        float rs = rsqrtf(var + 1e-5f);
        float4 y;
        y.x = (v0 - mu) * rs * g4.x + be4.x;
        y.y = (v1 - mu) * rs * g4.y + be4.y;
        y.z = (v2 - mu) * rs * g4.z + be4.z;
        y.w = (v3 - mu) * rs * g4.w + be4.w;
        *(float4*)(out + (size_t)n * 128 + lane * 4) = y;
    }
}

// ---------------------------------------------------------------------------
extern "C" void kernel_launch(void* const* d_in, const int* in_sizes, int n_in,
                              void* d_out, int out_size)
{
    const float* x    = (const float*)d_in[0];
    const void*  ei   = d_in[1];
    const float* ea   = (const float*)d_in[2];
    const float* Wl   = (const float*)d_in[3];
    const float* bl   = (const float*)d_in[4];
    const float* Wr   = (const float*)d_in[5];
    const float* br   = (const float*)d_in[6];
    const float* We   = (const float*)d_in[7];
    const float* att  = (const float*)d_in[8];
    const float* bias = (const float*)d_in[9];
    const float* gam  = (const float*)d_in[10];
    const float* bet  = (const float*)d_in[11];

    int N = in_sizes[0] / 128;
    int E = in_sizes[1] / 2;
    int nb = (N + SCAN_B - 1) / SCAN_B;

    dim3 ggrid((N + 63) / 64, 2);

    // Fork/join streams + events. Created per call (host-side objects, no
    // device allocation). NOT destroyed: destroying a stream/event that is
    // participating in an active capture is illegal; the handful of harness
    // invocations leak only a few host objects.
    cudaStream_t s1;
    cudaStreamCreateWithFlags(&s1, cudaStreamNonBlocking);
    cudaEvent_t evFork, evJoin;
    cudaEventCreateWithFlags(&evFork, cudaEventDisableTiming);
    cudaEventCreateWithFlags(&evJoin, cudaEventDisableTiming);

    // launch 0: kinit on origin stream (zeroed counts + is64 for both arms)
    kinit<<<(N + 255) / 256, 256>>>((const unsigned int*)ei, E, N);
    cudaEventRecord(evFork, 0);
    cudaStreamWaitEvent(s1, evFork, 0);

    // CSR arm begins on s1; compute arm continues on origin stream.
    khist<<<(E + 255) / 256, 256, 0, s1>>>(ei, E);                    // launch 1
    k_gemm<<<ggrid, 256>>>(x, Wl, bl, Wr, br, N);                     // launch 2
    k_logit<<<296, 256>>>(ei, ea, We, att, E);                        // launch 3 (profiled)
    kscan1<<<nb, SCAN_B, 0, s1>>>(N);                                 // launch 4
    kscan3<<<nb, SCAN_B, 0, s1>>>(N, nb);                             // launch 5
    kscatter<<<(E + 255) / 256, 256, 0, s1>>>(ei, E);                 // launch 6
    cudaEventRecord(evJoin, s1);
    cudaStreamWaitEvent(0, evJoin, 0);
    k_fused<<<444, 256>>>(bias, gam, bet, x, (float*)d_out, N);       // launch 7
}